// round 6
// baseline (speedup 1.0000x reference)
#include <cuda_runtime.h>
#include <cstddef>

#define NN 100000
#define DD 128
#define EE_MAX 600000
#define LL_MAX 200000

__device__ float g_agg[(size_t)NN * DD];
__device__ float g_x1 [(size_t)NN * DD];
__device__ float g_x2 [(size_t)NN * DD];
__device__ float g_inv[NN];
__device__ int   g_cnt[NN];

// ---------------------------------------------------------------------------
__global__ void deg_kernel(const int* __restrict__ dst, int e) {
    int i = blockIdx.x * blockDim.x + threadIdx.x;
    if (i < e) atomicAdd(&g_cnt[dst[i]], 1);
}

__global__ void inv_kernel(int n) {
    int i = blockIdx.x * blockDim.x + threadIdx.x;
    if (i < n) g_inv[i] = 1.0f / fmaxf((float)g_cnt[i], 1.0f);
}

// ---------------------------------------------------------------------------
__global__ void scatter_kernel(const float* __restrict__ x,
                               const int* __restrict__ src,
                               const int* __restrict__ dst, int e) {
    int w    = (blockIdx.x * blockDim.x + threadIdx.x) >> 5;
    int lane = threadIdx.x & 31;
    if (w >= e) return;
    int s = __ldg(src + w);
    int d = __ldg(dst + w);
    float4 v = *(const float4*)(x + (size_t)s * DD + lane * 4);
    atomicAdd((float4*)(g_agg + (size_t)d * DD + lane * 4), v);
}

// ---------------------------------------------------------------------------
// Packed dual-GEMM SAGE layer, 8 rows/warp, TILE_ROWS=128, split-K staging.
//   out = act( (agg*inv) @ Wl + b + xin @ Wr )
// ---------------------------------------------------------------------------
#define TILE_ROWS 128
#define KHALF 64
#define GEMM_THREADS 512
// floats: Wi 128*128*2 = 32768, AXs 128*64*2 = 16384, bias 128
#define GEMM_SMEM_FLOATS (32768 + 16384 + 128)
#define GEMM_SMEM_BYTES  (GEMM_SMEM_FLOATS * 4)

typedef unsigned long long ull;

__device__ __forceinline__ void ffma2(ull& d, ull a, ull b) {
    asm volatile("fma.rn.f32x2 %0, %1, %2, %0;" : "+l"(d) : "l"(a), "l"(b));
}

__global__ __launch_bounds__(GEMM_THREADS, 1)
void sage_gemm_kernel(const float* __restrict__ agg,
                      const float* __restrict__ xin,
                      const float* __restrict__ Wl,
                      const float* __restrict__ bias,
                      const float* __restrict__ Wr,
                      float* __restrict__ out,
                      int n, int do_relu) {
    extern __shared__ float sm[];
    float* Wi  = sm;                         // [128 k][128 c] ull pairs (wl,wr)
    float* AXs = Wi + 32768;                 // [128 row][64 kk] ull pairs (a,x)
    float* bs  = AXs + TILE_ROWS * KHALF * 2;

    const int tid = threadIdx.x;

    // Interleave weights once per persistent block
    for (int i = tid; i < 4096; i += GEMM_THREADS) {
        float4 l = ((const float4*)Wl)[i];
        float4 r = ((const float4*)Wr)[i];
        ((float4*)Wi)[i * 2 + 0] = make_float4(l.x, r.x, l.y, r.y);
        ((float4*)Wi)[i * 2 + 1] = make_float4(l.z, r.z, l.w, r.w);
    }
    if (tid < DD) bs[tid] = bias[tid];

    const int lane = tid & 31;   // base column
    const int rg   = tid >> 5;   // warp -> row group of 8
    const int r0   = rg * 8;

    const ull* Wiu = (const ull*)Wi;   // [k*128 + c]
    const ull* AXu = (const ull*)AXs;  // [row*64 + kk]

    const int ntiles = (n + TILE_ROWS - 1) / TILE_ROWS;
    for (int t = blockIdx.x; t < ntiles; t += gridDim.x) {
        const int base = t * TILE_ROWS;

        ull acc[8][4];
        #pragma unroll
        for (int r = 0; r < 8; r++)
            #pragma unroll
            for (int j = 0; j < 4; j++) acc[r][j] = 0ull;

        #pragma unroll
        for (int half = 0; half < 2; half++) {
            const int k0 = half * KHALF;
            __syncthreads();   // previous AXs consumption done
            // Stage (a,x) for k in [k0, k0+64): 128 rows x 16 float4-chunks
            for (int i = tid; i < TILE_ROWS * 16; i += GEMM_THREADS) {
                int row = i >> 4, c4 = i & 15;
                int gr = base + row;
                if (gr < n) {
                    float inv = g_inv[gr];
                    const float4* ap = (const float4*)(agg + (size_t)gr * DD + k0);
                    const float4* xp = (const float4*)(xin + (size_t)gr * DD + k0);
                    float4 a = ap[c4];
                    float4 x = xp[c4];
                    a.x *= inv; a.y *= inv; a.z *= inv; a.w *= inv;
                    float4* dst4 = (float4*)(AXs + (row * KHALF + c4 * 4) * 2);
                    dst4[0] = make_float4(a.x, x.x, a.y, x.y);
                    dst4[1] = make_float4(a.z, x.z, a.w, x.w);
                }
            }
            __syncthreads();

            #pragma unroll 4
            for (int kk = 0; kk < KHALF; kk += 2) {
                const int k = k0 + kk;
                ull w0[4], w1[4];
                #pragma unroll
                for (int j = 0; j < 4; j++) {
                    w0[j] = Wiu[(k    ) * DD + lane + 32 * j];
                    w1[j] = Wiu[(k + 1) * DD + lane + 32 * j];
                }
                #pragma unroll
                for (int r = 0; r < 8; r++) {
                    ulonglong2 ax = *(const ulonglong2*)(AXu + (r0 + r) * KHALF + kk);
                    #pragma unroll
                    for (int j = 0; j < 4; j++) {
                        ffma2(acc[r][j], ax.x, w0[j]);
                        ffma2(acc[r][j], ax.y, w1[j]);
                    }
                }
            }
        }

        // Epilogue: fold (accA + accX) + bias, optional relu
        #pragma unroll
        for (int r = 0; r < 8; r++) {
            int gr = base + r0 + r;
            if (gr < n) {
                #pragma unroll
                for (int j = 0; j < 4; j++) {
                    int c = lane + 32 * j;
                    float2 v = *(float2*)&acc[r][j];
                    float s = v.x + v.y + bs[c];
                    if (do_relu) s = fmaxf(s, 0.f);
                    out[(size_t)gr * DD + c] = s;
                }
            }
        }
    }
}

// ---------------------------------------------------------------------------
__global__ void predict_kernel(const int* __restrict__ s,
                               const int* __restrict__ d,
                               const float* __restrict__ Wlin,
                               const float* __restrict__ blin,
                               float* __restrict__ out, int L) {
    int w    = (blockIdx.x * blockDim.x + threadIdx.x) >> 5;
    int lane = threadIdx.x & 31;
    if (w >= L) return;
    int si = __ldg(s + w);
    int di = __ldg(d + w);
    float4 a  = *(const float4*)(g_x2 + (size_t)si * DD + lane * 4);
    float4 b  = *(const float4*)(g_x2 + (size_t)di * DD + lane * 4);
    float4 w0 = *(const float4*)(Wlin + lane * 4);
    float4 w1 = *(const float4*)(Wlin + DD + lane * 4);
    float acc = a.x * w0.x + a.y * w0.y + a.z * w0.z + a.w * w0.w
              + b.x * w1.x + b.y * w1.y + b.z * w1.z + b.w * w1.w;
    #pragma unroll
    for (int o = 16; o > 0; o >>= 1)
        acc += __shfl_down_sync(0xFFFFFFFFu, acc, o);
    if (lane == 0) out[w] = acc + __ldg(blin);
}

// ---------------------------------------------------------------------------
extern "C" void kernel_launch(void* const* d_in, const int* in_sizes, int n_in,
                              void* d_out, int out_size) {
    const int*   ei   = (const int*)d_in[0];
    const int*   eli  = (const int*)d_in[1];
    const float* emb  = (const float*)d_in[2];
    const float* W1l  = (const float*)d_in[3];
    const float* b1   = (const float*)d_in[4];
    const float* W1r  = (const float*)d_in[5];
    const float* W2l  = (const float*)d_in[6];
    const float* b2   = (const float*)d_in[7];
    const float* W2r  = (const float*)d_in[8];
    const float* Wlin = (const float*)d_in[9];
    const float* blin = (const float*)d_in[10];
    float*       out  = (float*)d_out;

    const int E = in_sizes[0] / 2;
    const int L = in_sizes[1] / 2;
    const int N = in_sizes[2] / DD;

    const int* src = ei;
    const int* dst = ei + E;
    const int* ls  = eli;
    const int* ld  = eli + L;

    void* p_agg = nullptr; cudaGetSymbolAddress(&p_agg, g_agg);
    void* p_cnt = nullptr; cudaGetSymbolAddress(&p_cnt, g_cnt);

    cudaFuncSetAttribute(sage_gemm_kernel,
                         cudaFuncAttributeMaxDynamicSharedMemorySize,
                         GEMM_SMEM_BYTES);

    float* x1 = nullptr; cudaGetSymbolAddress((void**)&x1, g_x1);
    float* agg = (float*)p_agg;
    float* x2 = nullptr; cudaGetSymbolAddress((void**)&x2, g_x2);

    const int scatter_blocks = ((size_t)E * 32 + 255) / 256;
    const int gemm_grid = 148;

    cudaMemsetAsync(p_cnt, 0, sizeof(int) * (size_t)N);
    cudaMemsetAsync(p_agg, 0, sizeof(float) * (size_t)N * DD);
    deg_kernel<<<(E + 255) / 256, 256>>>(dst, E);
    inv_kernel<<<(N + 255) / 256, 256>>>(N);

    scatter_kernel<<<scatter_blocks, 256>>>(emb, src, dst, E);
    sage_gemm_kernel<<<gemm_grid, GEMM_THREADS, GEMM_SMEM_BYTES>>>(
        agg, emb, W1l, b1, W1r, x1, N, 1);

    cudaMemsetAsync(p_agg, 0, sizeof(float) * (size_t)N * DD);
    scatter_kernel<<<scatter_blocks, 256>>>(x1, src, dst, E);
    sage_gemm_kernel<<<gemm_grid, GEMM_THREADS, GEMM_SMEM_BYTES>>>(
        agg, x1, W2l, b2, W2r, x2, N, 0);

    predict_kernel<<<((size_t)L * 32 + 127) / 128, 128>>>(ls, ld, Wlin, blin, out, L);
}